// round 15
// baseline (speedup 1.0000x reference)
#include <cuda_runtime.h>
#include <cuda_bf16.h>
#include <math.h>
#include <stdint.h>

// Problem constants (reference: N=1024, L=30, G=10000, NB=64)
#define LDIM    30
#define ZROW    32           // padded z row (2 zero pads)
#define GPB     64           // genes per block tile (2 threads per gene)
#define THREADS 128
#define CHUNK   64           // cells staged per z chunk
#define NMAX    1024

__device__ __forceinline__ float softplus_fast(float x) {
    // max(x,0) + log1p(exp(-|x|)); fast intrinsics (rel err ~1e-6 << 1e-3 budget)
    return fmaxf(x, 0.0f) + __logf(1.0f + __expf(-fabsf(x)));
}

__device__ __forceinline__ void cp_async16(unsigned int saddr, const void* gptr) {
    asm volatile("cp.async.cg.shared.global [%0], [%1], 16;\n" :: "r"(saddr), "l"(gptr));
}
__device__ __forceinline__ void cp_commit() { asm volatile("cp.async.commit_group;\n" ::: "memory"); }
__device__ __forceinline__ void cp_wait0()  { asm volatile("cp.async.wait_group 0;\n" ::: "memory"); }

// ---------------------------------------------------------------------------
// grid = (ceil(G/GPB), NB + 1), block = 128.
//   y < NB : decoder for batch y, 64-gene tile. TWO threads per gene:
//            lane<16 handles l=[0,16), lane>=16 handles l=[16,30)+pads.
//            Each thread holds only c[16] -> ~48 regs -> occupancy ceiling
//            rises from 50% (64-reg RF cap) to ~62%.
//            Partial dots combined with shfl.bfly(16); lane<16 stores.
//   y == NB: inverse_dispersion = exp(px_r)
// ---------------------------------------------------------------------------
__global__ __launch_bounds__(THREADS, 10) void fused_decoder_kernel(
    const float* __restrict__ z,      // [N, L]
    const int*   __restrict__ bc,     // [N]
    const float* __restrict__ sf,     // [N, 1]
    const float* __restrict__ W,      // [L, G]
    const float* __restrict__ A,      // [NB, G, L]
    const float* __restrict__ bemb,   // [NB, G]
    const float* __restrict__ px_r,   // [G]
    float* __restrict__ out,          // [N, G] ++ [G]
    int N, int G, int NB)
{
    // ---- exp(px_r) slice ----
    if (blockIdx.y == (unsigned)NB) {
        float* od = out + (size_t)N * G;
        for (int g = blockIdx.x * THREADS + threadIdx.x; g < G; g += gridDim.x * THREADS)
            od[g] = __expf(px_r[g]);
        return;
    }

    __shared__ float as[GPB * LDIM];        // 7.5 KB  A tile (cp.async staged)
    __shared__ float zs[CHUNK * ZROW];      //  8 KB   z chunk, padded rows
    __shared__ int   cells[NMAX + 4];       //  4 KB   cell list (padded to mult 4)
    __shared__ float sfs[CHUNK];
    __shared__ int   scount;

    const int tid   = threadIdx.x;
    const int b     = blockIdx.y;
    const int gbase = blockIdx.x * GPB;
    const int nst   = min(GPB, G - gbase);

    // ---- kick off A tile load first (hide behind compaction) ----
    {
        const float*  srcf = A + ((size_t)b * G + gbase) * LDIM;
        unsigned int  dst  = (unsigned int)__cvta_generic_to_shared(&as[0]);
        const int w4 = (nst * LDIM) >> 2;            // nst*30 divisible by 4 here
        const float4* src4 = (const float4*)srcf;
        for (int i = tid; i < w4; i += THREADS) cp_async16(dst + i * 16, src4 + i);
    }
    cp_commit();

    // ---- compact this batch's cell list (bc: 4 KB, L2-hot) ----
    if (tid == 0) scount = 0;
    __syncthreads();
    for (int n = tid; n < N; n += THREADS) {
        if (bc[n] == b) {
            int p = atomicAdd(&scount, 1);
            cells[p] = n;
        }
    }
    cp_wait0();
    __syncthreads();                       // cells/scount + as[] visible everywhere
    const int ncell = scount;
    if (ncell == 0) return;                // uniform across block
    const int ncp = (ncell + 3) & ~3;      // pad to multiple of 4
    if (tid < ncp - ncell) cells[ncell + tid] = cells[ncell - 1];  // duplicate last

    // ---- thread mapping: 2 threads per gene (half-L split) ----
    const int lane = tid & 31;
    const int h    = lane >> 4;            // 0: l=[0,16)   1: l=[16,32) (pads 0)
    const int gl   = (tid >> 5) * 16 + (lane & 15);   // local gene 0..63
    const int g    = gbase + gl;
    const bool act = (gl < nst);

    float c[16];
    float binit = 0.0f;
    if (act) {
        #pragma unroll
        for (int k = 0; k < 16; k++) {
            int l = h * 16 + k;
            c[k] = (l < LDIM) ? (W[(size_t)l * G + g] + as[gl * LDIM + l]) : 0.0f;
        }
        if (h == 0) binit = bemb[(size_t)b * G + g];   // bias on half 0 only
    }
    __syncthreads();                        // padding writes visible before staging

    for (int cc = 0; cc < ncp; cc += CHUNK) {
        const int nc = min(CHUNK, ncp - cc);        // multiple of 4
        __syncthreads();                    // previous chunk's zs reads complete
        // stage z rows (padded to 32, zero pads) + size factors
        for (int i = tid; i < nc * (LDIM / 2); i += THREADS) {
            int ci = i / (LDIM / 2), l = i - ci * (LDIM / 2);
            float2 v = *(const float2*)(z + (size_t)cells[cc + ci] * LDIM + 2 * l);
            *(float2*)(zs + ci * ZROW + 2 * l) = v;
        }
        for (int i = tid; i < nc; i += THREADS) {
            zs[i * ZROW + 30] = 0.0f;
            zs[i * ZROW + 31] = 0.0f;
            sfs[i] = sf[cells[cc + i]];
        }
        __syncthreads();

        for (int j = 0; j < nc; j += 4) {
            // each thread reads ONLY its half (16 floats = 2 LDS.128) per cell
            const float4* zp = (const float4*)(zs + j * ZROW + h * 16);
            float a0 = binit, a1 = binit, a2 = binit, a3 = binit;
            {
                float4 v0 = zp[0], v1 = zp[1];                 // cell j
                a0 = fmaf(c[ 0], v0.x, a0); a0 = fmaf(c[ 1], v0.y, a0);
                a0 = fmaf(c[ 2], v0.z, a0); a0 = fmaf(c[ 3], v0.w, a0);
                a0 = fmaf(c[ 4], v1.x, a0); a0 = fmaf(c[ 5], v1.y, a0);
                a0 = fmaf(c[ 6], v1.z, a0); a0 = fmaf(c[ 7], v1.w, a0);
                float4 v2 = zp[2], v3 = zp[3];
                a0 = fmaf(c[ 8], v2.x, a0); a0 = fmaf(c[ 9], v2.y, a0);
                a0 = fmaf(c[10], v2.z, a0); a0 = fmaf(c[11], v2.w, a0);
                a0 = fmaf(c[12], v3.x, a0); a0 = fmaf(c[13], v3.y, a0);
                a0 = fmaf(c[14], v3.z, a0); a0 = fmaf(c[15], v3.w, a0);
            }
            // NOTE: zp row stride is ZROW floats = 8 float4s; half offset fixed.
            {
                const float4* zq = zp + (ZROW / 4);            // cell j+1
                float4 v0 = zq[0], v1 = zq[1];
                a1 = fmaf(c[ 0], v0.x, a1); a1 = fmaf(c[ 1], v0.y, a1);
                a1 = fmaf(c[ 2], v0.z, a1); a1 = fmaf(c[ 3], v0.w, a1);
                a1 = fmaf(c[ 4], v1.x, a1); a1 = fmaf(c[ 5], v1.y, a1);
                a1 = fmaf(c[ 6], v1.z, a1); a1 = fmaf(c[ 7], v1.w, a1);
                float4 v2 = zq[2], v3 = zq[3];
                a1 = fmaf(c[ 8], v2.x, a1); a1 = fmaf(c[ 9], v2.y, a1);
                a1 = fmaf(c[10], v2.z, a1); a1 = fmaf(c[11], v2.w, a1);
                a1 = fmaf(c[12], v3.x, a1); a1 = fmaf(c[13], v3.y, a1);
                a1 = fmaf(c[14], v3.z, a1); a1 = fmaf(c[15], v3.w, a1);
            }
            {
                const float4* zq = zp + 2 * (ZROW / 4);        // cell j+2
                float4 v0 = zq[0], v1 = zq[1];
                a2 = fmaf(c[ 0], v0.x, a2); a2 = fmaf(c[ 1], v0.y, a2);
                a2 = fmaf(c[ 2], v0.z, a2); a2 = fmaf(c[ 3], v0.w, a2);
                a2 = fmaf(c[ 4], v1.x, a2); a2 = fmaf(c[ 5], v1.y, a2);
                a2 = fmaf(c[ 6], v1.z, a2); a2 = fmaf(c[ 7], v1.w, a2);
                float4 v2 = zq[2], v3 = zq[3];
                a2 = fmaf(c[ 8], v2.x, a2); a2 = fmaf(c[ 9], v2.y, a2);
                a2 = fmaf(c[10], v2.z, a2); a2 = fmaf(c[11], v2.w, a2);
                a2 = fmaf(c[12], v3.x, a2); a2 = fmaf(c[13], v3.y, a2);
                a2 = fmaf(c[14], v3.z, a2); a2 = fmaf(c[15], v3.w, a2);
            }
            {
                const float4* zq = zp + 3 * (ZROW / 4);        // cell j+3
                float4 v0 = zq[0], v1 = zq[1];
                a3 = fmaf(c[ 0], v0.x, a3); a3 = fmaf(c[ 1], v0.y, a3);
                a3 = fmaf(c[ 2], v0.z, a3); a3 = fmaf(c[ 3], v0.w, a3);
                a3 = fmaf(c[ 4], v1.x, a3); a3 = fmaf(c[ 5], v1.y, a3);
                a3 = fmaf(c[ 6], v1.z, a3); a3 = fmaf(c[ 7], v1.w, a3);
                float4 v2 = zq[2], v3 = zq[3];
                a3 = fmaf(c[ 8], v2.x, a3); a3 = fmaf(c[ 9], v2.y, a3);
                a3 = fmaf(c[10], v2.z, a3); a3 = fmaf(c[11], v2.w, a3);
                a3 = fmaf(c[12], v3.x, a3); a3 = fmaf(c[13], v3.y, a3);
                a3 = fmaf(c[14], v3.z, a3); a3 = fmaf(c[15], v3.w, a3);
            }
            // combine the two halves (both lanes end with the full dot)
            a0 += __shfl_xor_sync(0xffffffffu, a0, 16);
            a1 += __shfl_xor_sync(0xffffffffu, a1, 16);
            a2 += __shfl_xor_sync(0xffffffffu, a2, 16);
            a3 += __shfl_xor_sync(0xffffffffu, a3, 16);

            if (act & (h == 0)) {
                // duplicate-padded cells store identical values: benign
                out[(size_t)cells[cc + j    ] * G + g] = softplus_fast(a0) * sfs[j    ];
                out[(size_t)cells[cc + j + 1] * G + g] = softplus_fast(a1) * sfs[j + 1];
                out[(size_t)cells[cc + j + 2] * G + g] = softplus_fast(a2) * sfs[j + 2];
                out[(size_t)cells[cc + j + 3] * G + g] = softplus_fast(a3) * sfs[j + 3];
            }
        }
    }
}

// ---------------------------------------------------------------------------
// Inputs (metadata order): z, batch_covariate, size_factor, W_amat, A_emb,
//                          b_emb, px_r.  Output: mean [N,G] ++ inv_disp [G].
// ---------------------------------------------------------------------------
extern "C" void kernel_launch(void* const* d_in, const int* in_sizes, int n_in,
                              void* d_out, int out_size) {
    const float* z    = (const float*)d_in[0];
    const int*   bc   = (const int*)  d_in[1];
    const float* sf   = (const float*)d_in[2];
    const float* W    = (const float*)d_in[3];
    const float* A    = (const float*)d_in[4];
    const float* bemb = (const float*)d_in[5];
    const float* px_r = (const float*)d_in[6];
    float* out = (float*)d_out;

    const int N  = in_sizes[1];        // 1024
    const int G  = in_sizes[6];        // 10000
    const int NB = in_sizes[5] / G;    // 64

    dim3 grid((G + GPB - 1) / GPB, NB + 1);
    fused_decoder_kernel<<<grid, THREADS>>>(z, bc, sf, W, A, bemb, px_r, out, N, G, NB);
}